// round 8
// baseline (speedup 1.0000x reference)
#include <cuda_runtime.h>
#include <cstdio>
#include <cstdint>

#define BB 4
#define NSS 96
#define TT 8
#define HD 256
#define H4 1024
#define NW 1280
#define NN 97
#define NLAY 6
#define ROWS (BB*NN)     // 388
#define SEQS (BB*NSS)    // 384
#define TOK  (SEQS*TT)   // 3072

// ---------------- scratch -----------------------------------------------------
__device__ float g_xw[TOK*H4];
__device__ float g_Wt[HD*H4];          // Wh_s gate-interleaved [k][h*4+g]
__device__ float g_B1[HD*NW];          // [Wh_e | W_hk]
__device__ float g_B2[HD*NW];          // [Wx_e | W_sd]
__device__ float g_c0[SEQS*HD];
__device__ float g_hA[SEQS*HD];
__device__ float g_hB[SEQS*HD];
__device__ float g_pref[ROWS*HD];
__device__ float g_MeMs[HD*NW];
__device__ float g_pmS[ROWS*NW];       // cols 0-1023 = pm4, 1024+ = prS
__device__ float g_be[H4];
__device__ float g_bs[HD];
__device__ float g_S2[BB*NN*NN];
__device__ float g_u[ROWS*H4];
__device__ float g_hk[ROWS*HD];        // relu(h@W_hk + b_hk) * W_d1[:256]
__device__ float g_w[BB*NN*NN];
__device__ float g_cX[ROWS*HD], g_hX[ROWS*HD];
__device__ float g_cY[ROWS*HD], g_hY[ROWS*HD];
__device__ float g_pX[ROWS], g_pY[ROWS];

// exp-based gates (accurate path; used in statement LSTM + setup)
__device__ __forceinline__ float sigf(float x) {
    return __fdividef(1.0f, 1.0f + __expf(-x));
}
__device__ __forceinline__ float tanhr(float x) {
    return 2.0f * __fdividef(1.0f, 1.0f + __expf(-2.0f * x)) - 1.0f;
}

// HW-tanh gates (1 MUFU op each; used in the MUFU-bound agg hot loop)
__device__ __forceinline__ float tanhw(float x) {
    float y;
    asm("tanh.approx.f32 %0, %1;" : "=f"(y) : "f"(x));
    return y;
}
__device__ __forceinline__ float sigw(float x) {
    return fmaf(0.5f, tanhw(0.5f * x), 0.5f);
}

__device__ __forceinline__ float to_tf32(float x) {
    uint32_t o;
    asm("cvt.rna.tf32.f32 %0, %1;" : "=r"(o) : "f"(x));
    return __uint_as_float(o);
}

__device__ __forceinline__ void mma_tf32(float& c0, float& c1, float& c2, float& c3,
                                         float a0, float a1, float a2, float a3,
                                         float b0, float b1) {
    asm volatile(
        "mma.sync.aligned.m16n8k8.row.col.f32.tf32.tf32.f32 "
        "{%0,%1,%2,%3},{%4,%5,%6,%7},{%8,%9},{%0,%1,%2,%3};"
        : "+f"(c0), "+f"(c1), "+f"(c2), "+f"(c3)
        : "r"(__float_as_uint(a0)), "r"(__float_as_uint(a1)),
          "r"(__float_as_uint(a2)), "r"(__float_as_uint(a3)),
          "r"(__float_as_uint(b0)), "r"(__float_as_uint(b1)));
}

// ---------------- tf32 MMA GEMM, K=256, tile 64x64, 256 threads ---------------
// EPI: 0 = plain (+opt bias), 1 = LSTM gates fused, 2 = layer (u + hk)
#define SA_STRIDE 36
#define SB_STRIDE 72
#define BUF_STRIDE 68
template<int EPI>
__global__ __launch_bounds__(256)
void mma_gemm(const float* __restrict__ A, const int* __restrict__ gidx,
              const float* __restrict__ B, const float* __restrict__ bias,
              float* __restrict__ C, int M, int N,
              const float* __restrict__ xw_t, float* __restrict__ c_st,
              float* __restrict__ hout,
              const float* __restrict__ be, const float* __restrict__ pmS,
              const float* __restrict__ b_hk, const float* __restrict__ W_d1,
              float* __restrict__ u, float* __restrict__ hkbuf) {
    __shared__ float smem[64 * SA_STRIDE + 32 * SB_STRIDE];   // 4608 floats
    float* sA = smem;                       // [64][36]  (m,k)
    float* sB = smem + 64 * SA_STRIDE;      // [32][72]  (k,n)
    const int tid = threadIdx.x;
    const int lane = tid & 31, warp = tid >> 5;
    const int wm = warp >> 1, wn = warp & 1;     // 4x2 warp grid
    const int g = lane >> 2, tg = lane & 3;
    const int bm = blockIdx.x * 64, bn = blockIdx.y * 64;
    const int K = HD;

    float acc[4][4];
#pragma unroll
    for (int a = 0; a < 4; a++)
#pragma unroll
        for (int b = 0; b < 4; b++) acc[a][b] = 0.f;

    for (int k0 = 0; k0 < K; k0 += 32) {
#pragma unroll
        for (int l = 0; l < 2; l++) {
            int t = tid + l * 256;
            int r = t >> 3;
            int kc = (t & 7) << 2;
            int row = bm + r;
            float4 v = make_float4(0.f, 0.f, 0.f, 0.f);
            if (row < M) {
                int ar = gidx ? gidx[row] : row;
                v = *(const float4*)(A + (size_t)ar * K + k0 + kc);
            }
            float* d = sA + r * SA_STRIDE + kc;
            d[0] = to_tf32(v.x); d[1] = to_tf32(v.y);
            d[2] = to_tf32(v.z); d[3] = to_tf32(v.w);
        }
#pragma unroll
        for (int l = 0; l < 2; l++) {
            int t = tid + l * 256;
            int kk = t >> 4;
            int c = (t & 15) << 2;
            float4 v = *(const float4*)(B + (size_t)(k0 + kk) * N + bn + c);
            float* d = sB + kk * SB_STRIDE + c;
            d[0] = to_tf32(v.x); d[1] = to_tf32(v.y);
            d[2] = to_tf32(v.z); d[3] = to_tf32(v.w);
        }
        __syncthreads();
#pragma unroll
        for (int k8 = 0; k8 < 4; k8++) {
            int kb = k8 * 8;
            float a0 = sA[(wm * 16 + g) * SA_STRIDE + kb + tg];
            float a1 = sA[(wm * 16 + g + 8) * SA_STRIDE + kb + tg];
            float a2 = sA[(wm * 16 + g) * SA_STRIDE + kb + tg + 4];
            float a3 = sA[(wm * 16 + g + 8) * SA_STRIDE + kb + tg + 4];
#pragma unroll
            for (int nt = 0; nt < 4; nt++) {
                int nc = wn * 32 + nt * 8 + g;
                float b0 = sB[(kb + tg) * SB_STRIDE + nc];
                float b1 = sB[(kb + tg + 4) * SB_STRIDE + nc];
                mma_tf32(acc[nt][0], acc[nt][1], acc[nt][2], acc[nt][3],
                         a0, a1, a2, a3, b0, b1);
            }
        }
        __syncthreads();
    }

    if (EPI == 1) {
        // stage to smem buf [64][68], regroup gates, apply LSTM
        float* buf = smem;
#pragma unroll
        for (int nt = 0; nt < 4; nt++)
#pragma unroll
            for (int e = 0; e < 4; e++) {
                int lr = wm * 16 + g + ((e >> 1) ? 8 : 0);
                int lc = wn * 32 + nt * 8 + tg * 2 + (e & 1);
                buf[lr * BUF_STRIDE + lc] = acc[nt][e];
            }
        __syncthreads();
#pragma unroll
        for (int l = 0; l < 4; l++) {
            int pi = tid + l * 256;          // 1024 = 64 rows x 16 hidden
            int lr = pi & 63;
            int lh = pi >> 6;                // 0..15
            int row = bm + lr;
            int hh = (bn >> 2) + lh;         // global hidden unit
            float4 z4 = *(const float4*)(buf + lr * BUF_STRIDE + lh * 4);
            const float* xr = xw_t + (size_t)row * (TT * H4);
            float zi = z4.x + xr[hh];
            float zf = z4.y + xr[HD + hh];
            float zg = z4.z + xr[2 * HD + hh];
            float zo = z4.w + xr[3 * HD + hh];
            size_t idx = (size_t)row * HD + hh;
            float cp = c_st[idx];
            float c2 = sigf(zf) * cp + sigf(zi) * tanhr(zg);
            c_st[idx] = c2;
            hout[idx] = sigf(zo) * tanhr(c2);
        }
        return;
    }

#pragma unroll
    for (int nt = 0; nt < 4; nt++)
#pragma unroll
        for (int e = 0; e < 4; e++) {
            int row = bm + wm * 16 + g + ((e >> 1) ? 8 : 0);
            int col = bn + wn * 32 + nt * 8 + tg * 2 + (e & 1);
            if (row >= M) continue;
            float v = acc[nt][e];
            if (EPI == 0) {
                C[(size_t)row * N + col] = v + (bias ? bias[col] : 0.f);
            } else {  // EPI == 2
                if (col < H4) {
                    u[(size_t)row * H4 + col] = v + be[col] - pmS[(size_t)row * NW + col];
                } else {
                    int cc = col - H4;
                    hkbuf[(size_t)row * HD + cc] =
                        fmaxf(v + b_hk[cc], 0.f) * W_d1[cc];
                }
            }
        }
}

// ---------------- small helpers -----------------------------------------------
__global__ void wt_kernel(const float* __restrict__ Wh, float* __restrict__ Wt) {
    int idx = blockIdx.x * 256 + threadIdx.x;
    if (idx >= HD * H4) return;
    int k = idx / H4, col = idx % H4;
    int g = col / HD, hh = col % HD;
    Wt[(size_t)k * H4 + hh * 4 + g] = Wh[idx];
}

// both merged B matrices in one launch: B1 = [Wh_e|W_hk], B2 = [Wx_e|W_sd]
__global__ void copyB2_kernel(const float* __restrict__ a1, const float* __restrict__ a2,
                              const float* __restrict__ b1, const float* __restrict__ b2,
                              float* __restrict__ d1, float* __restrict__ d2) {
    int idx = blockIdx.x * 256 + threadIdx.x;
    if (idx >= HD * NW) return;
    int k = idx / NW, c = idx % NW;
    d1[idx] = (c < H4) ? a1[(size_t)k * H4 + c] : a2[(size_t)k * HD + (c - H4)];
    d2[idx] = (c < H4) ? b1[(size_t)k * H4 + c] : b2[(size_t)k * HD + (c - H4)];
}

__global__ void lstm_gate0_kernel(const float* __restrict__ z, float* __restrict__ c,
                                  float* __restrict__ h) {
    int idx = blockIdx.x * blockDim.x + threadIdx.x;
    if (idx >= SEQS * HD) return;
    int s = idx / HD, hh = idx % HD;
    const float* zr = z + (size_t)s * (TT * H4);
    float zi = zr[hh], zg = zr[2 * HD + hh], zo = zr[3 * HD + hh];
    float c2 = sigf(zi) * tanhr(zg);
    h[idx] = sigf(zo) * tanhr(c2);
    c[idx] = c2;
}

__global__ void cumsum_kernel(const float* __restrict__ stmt, float* __restrict__ pref) {
    int b = blockIdx.x, hh = threadIdx.x;
    float acc = 0.f;
    pref[(size_t)(b * NN) * HD + hh] = 0.f;
    for (int k = 1; k < NN; k++) {
        acc += stmt[(size_t)(b * NSS + k - 1) * HD + hh];
        pref[(size_t)(b * NN + k) * HD + hh] = acc;
    }
}

// both composed biases: be[1024] = b_se@Wx_e + b_e; bs[256] = b_se@W_sd + b_sd
__global__ void bias2_kernel(const float* __restrict__ b_se,
                             const float* __restrict__ Wx_e, const float* __restrict__ b_e,
                             const float* __restrict__ W_sd, const float* __restrict__ b_sd,
                             float* __restrict__ be, float* __restrict__ bs) {
    int n = blockIdx.x * blockDim.x + threadIdx.x;
    if (n < H4) {
        float acc = b_e[n];
        for (int k = 0; k < HD; k++) acc += b_se[k] * Wx_e[(size_t)k * H4 + n];
        be[n] = acc;
    } else if (n < H4 + HD) {
        int c = n - H4;
        float acc = b_sd[c];
        for (int k = 0; k < HD; k++) acc += b_se[k] * W_sd[(size_t)k * HD + c];
        bs[c] = acc;
    }
}

__global__ void s2_kernel(const float* __restrict__ pmS, const float* __restrict__ bs,
                          const float* __restrict__ W_d1, float* __restrict__ S2) {
    int bi = blockIdx.x;
    int b = bi / NN;
    int lane = threadIdx.x & 31, warp = threadIdx.x >> 5;
    const float* pi = pmS + (size_t)bi * NW + H4;
    for (int j = warp; j < NN; j += 4) {
        const float* pj = pmS + (size_t)(b * NN + j) * NW + H4;
        float acc = 0.f;
#pragma unroll
        for (int l = 0; l < 8; l++) {
            int hh = lane + l * 32;
            float v = pj[hh] - pi[hh] + bs[hh];
            acc += fmaxf(v, 0.f) * W_d1[HD + hh];
        }
        for (int o = 16; o; o >>= 1) acc += __shfl_xor_sync(0xFFFFFFFFu, acc, o);
        if (lane == 0) S2[(size_t)bi * NN + j] = acc;
    }
}

__global__ void init_exec_kernel(const float* __restrict__ ia, const float* __restrict__ ib,
                                 float* __restrict__ c, float* __restrict__ h,
                                 float* __restrict__ p) {
    int idx = blockIdx.x * blockDim.x + threadIdx.x;
    if (idx < ROWS * HD) { c[idx] = ia[idx % HD]; h[idx] = ib[idx % HD]; }
    if (idx < ROWS) p[idx] = (idx % NN == 0) ? 1.f : 0.f;
}

// ---------------- per-layer: softmax (hk already reduced per element) ---------
__global__ void softmax_kernel(const float* __restrict__ hkbuf,
                               const float* __restrict__ S2, const float* __restrict__ b_d1,
                               const float* __restrict__ p, const int* __restrict__ clen,
                               int layer, float* __restrict__ w) {
    int bi = blockIdx.x, b = bi / NN, i = bi % NN;
    int tid = threadIdx.x;   // 256
    __shared__ float red[256];
    red[tid] = hkbuf[(size_t)bi * HD + tid];
    __syncthreads();
    for (int s = 128; s > 0; s >>= 1) {
        if (tid < s) red[tid] += red[tid + s];
        __syncthreads();
    }
    float a = red[0];
    __syncthreads();

    int len = clen[b] / TT;
    int j = tid;
    bool m = false;
    if (j < NN) {
        if (layer == 0)             m = (j == 1);
        else if (layer == NLAY - 1) m = (j == len);
        else                        m = ((j > i) && (j <= len)) || (j == len);
    }
    float logit = m ? (a + S2[(size_t)bi * NN + j] + b_d1[0]) : -1e30f;
    red[tid] = logit; __syncthreads();
    for (int s = 128; s > 0; s >>= 1) {
        if (tid < s) red[tid] = fmaxf(red[tid], red[tid + s]);
        __syncthreads();
    }
    float mx = red[0]; __syncthreads();
    float e = m ? __expf(logit - mx) : 0.f;
    red[tid] = e; __syncthreads();
    for (int s = 128; s > 0; s >>= 1) {
        if (tid < s) red[tid] += red[tid + s];
        __syncthreads();
    }
    float sum = red[0];
    if (j < NN) w[(size_t)bi * NN + j] = p[bi] * __fdividef(e, sum);
}

// ---------------- per-layer: gated aggregation (HW tanh gates) ----------------
__global__ void agg_kernel(const float* __restrict__ w, const float* __restrict__ pmS,
                           const float* __restrict__ u,
                           const float* __restrict__ cIn, const float* __restrict__ hIn,
                           float* __restrict__ cOut, float* __restrict__ hOut,
                           float* __restrict__ pOut) {
    int bj = blockIdx.x, b = bj / NN, j = bj % NN;
    int hh = threadIdx.x;  // 256
    __shared__ float sw[NN];
    if (hh < NN) sw[hh] = w[((size_t)(b * NN + hh)) * NN + j];
    __syncthreads();
    const float* pj = pmS + (size_t)bj * NW;
    float zj0 = pj[hh], zj1 = pj[HD + hh], zj2 = pj[2 * HD + hh], zj3 = pj[3 * HD + hh];
    float accC = 0.f, accH = 0.f, wsum = 0.f;
    for (int i = 0; i < NN; i++) {
        float wi = sw[i];
        wsum += wi;
        if (wi == 0.f) continue;
        int ri = b * NN + i;
        float cp, hp;
        if (j > i) {
            const float* ui = u + (size_t)ri * H4;
            float zi = zj0 + ui[hh];
            float zf = zj1 + ui[HD + hh];
            float zg = zj2 + ui[2 * HD + hh];
            float zo = zj3 + ui[3 * HD + hh];
            float cold = cIn[(size_t)ri * HD + hh];
            cp = sigw(zf) * cold + sigw(zi) * tanhw(zg);
            hp = sigw(zo) * tanhw(cp);
        } else {
            cp = cIn[(size_t)ri * HD + hh];
            hp = hIn[(size_t)ri * HD + hh];
        }
        accC += wi * cp;
        accH += wi * hp;
    }
    float inv = __fdividef(1.f, wsum + 1e-7f);
    cOut[(size_t)bj * HD + hh] = accC * inv;
    hOut[(size_t)bj * HD + hh] = accH * inv;
    if (hh == 0) pOut[bj] = wsum;
}

// ------------------------------------------------------------------------------
static float* sym(const void* s) {
    void* p = nullptr;
    cudaGetSymbolAddress(&p, s);
    return (float*)p;
}

extern "C" void kernel_launch(void* const* d_in, const int* in_sizes, int n_in,
                              void* d_out, int out_size) {
    const int*   ids    = (const int*)d_in[0];
    const int*   clen   = (const int*)d_in[1];
    const float* embed  = (const float*)d_in[2];
    const float* Wx_s   = (const float*)d_in[3];
    const float* Wh_s   = (const float*)d_in[4];
    const float* b_s    = (const float*)d_in[5];
    const float* W_se   = (const float*)d_in[6];
    const float* b_se   = (const float*)d_in[7];
    const float* Wx_e   = (const float*)d_in[8];
    const float* Wh_e   = (const float*)d_in[9];
    const float* b_e    = (const float*)d_in[10];
    const float* W_hk   = (const float*)d_in[11];
    const float* b_hk   = (const float*)d_in[12];
    const float* W_sd   = (const float*)d_in[13];
    const float* b_sd   = (const float*)d_in[14];
    const float* W_d1   = (const float*)d_in[15];
    const float* b_d1   = (const float*)d_in[16];
    const float* init_a = (const float*)d_in[17];
    const float* init_b = (const float*)d_in[18];

    float* xw   = sym(g_xw);
    float* Wt   = sym(g_Wt);
    float* B1   = sym(g_B1);
    float* B2   = sym(g_B2);
    float* c0   = sym(g_c0);
    float* hA   = sym(g_hA);
    float* hB   = sym(g_hB);
    float* pref = sym(g_pref);
    float* MeMs = sym(g_MeMs);
    float* pmS  = sym(g_pmS);
    float* be   = sym(g_be);
    float* bs   = sym(g_bs);
    float* S2   = sym(g_S2);
    float* uBuf = sym(g_u);
    float* hk   = sym(g_hk);
    float* wM   = sym(g_w);
    float* cX   = sym(g_cX);
    float* hX   = sym(g_hX);
    float* cY   = sym(g_cY);
    float* hY   = sym(g_hY);
    float* pX   = sym(g_pX);
    float* pY   = sym(g_pY);

    // 0) weight reshapes / merges
    wt_kernel<<<(HD * H4 + 255) / 256, 256>>>(Wh_s, Wt);
    copyB2_kernel<<<(HD * NW + 255) / 256, 256>>>(Wh_e, W_hk, Wx_e, W_sd, B1, B2);

    // 1) token projection: xw = embed[ids] @ Wx_s + b_s
    mma_gemm<0><<<dim3(TOK / 64, H4 / 64), 256>>>(
        embed, ids, Wx_s, b_s, xw, TOK, H4,
        nullptr, nullptr, nullptr, nullptr, nullptr, nullptr, nullptr, nullptr, nullptr);

    // 2) statement LSTM: step 0 elementwise, steps 1-7 fused MMA
    lstm_gate0_kernel<<<(SEQS * HD + 255) / 256, 256>>>(xw, c0, hA);
    float *hs = hA, *hd = hB;
    for (int t = 1; t < TT; t++) {
        mma_gemm<1><<<dim3(SEQS / 64, H4 / 64), 256>>>(
            hs, nullptr, Wt, nullptr, nullptr, SEQS, H4,
            xw + (size_t)t * H4, c0, hd,
            nullptr, nullptr, nullptr, nullptr, nullptr, nullptr);
        float* tmp = hs; hs = hd; hd = tmp;
    }

    // 3) prefix sums
    cumsum_kernel<<<BB, HD>>>(hs, pref);

    // 4) composed tables + biases
    mma_gemm<0><<<dim3(HD / 64, NW / 64), 256>>>(
        W_se, nullptr, B2, nullptr, MeMs, HD, NW,
        nullptr, nullptr, nullptr, nullptr, nullptr, nullptr, nullptr, nullptr, nullptr);
    mma_gemm<0><<<dim3((ROWS + 63) / 64, NW / 64), 256>>>(
        pref, nullptr, MeMs, nullptr, pmS, ROWS, NW,
        nullptr, nullptr, nullptr, nullptr, nullptr, nullptr, nullptr, nullptr, nullptr);
    bias2_kernel<<<(H4 + HD + 255) / 256, 256>>>(b_se, Wx_e, b_e, W_sd, b_sd, be, bs);

    // 5) layer-invariant logit term + exec init
    s2_kernel<<<ROWS, 128>>>(pmS, bs, W_d1, S2);
    init_exec_kernel<<<ROWS, 256>>>(init_a, init_b, cX, hX, pX);

    // 6) execution layers
    float *cS = cX, *hS = hX, *pS = pX, *cD = cY, *hD2 = hY, *pD = pY;
    for (int layer = 0; layer < NLAY; layer++) {
        mma_gemm<2><<<dim3((ROWS + 63) / 64, NW / 64), 256>>>(
            hS, nullptr, B1, nullptr, nullptr, ROWS, NW,
            nullptr, nullptr, nullptr,
            be, pmS, b_hk, W_d1, uBuf, hk);
        softmax_kernel<<<ROWS, 256>>>(hk, S2, b_d1, pS, clen, layer, wM);
        float* hOutPtr = (layer == NLAY - 1) ? (float*)d_out : hD2;
        agg_kernel<<<ROWS, 256>>>(wM, pmS, uBuf, cS, hS, cD, hOutPtr, pD);
        float* t;
        t = cS; cS = cD; cD = t;
        t = hS; hS = hD2; hD2 = t;
        t = pS; pS = pD; pD = t;
    }
}

// round 9
// speedup vs baseline: 1.1871x; 1.1871x over previous
#include <cuda_runtime.h>
#include <cstdio>
#include <cstdint>

#define BB 4
#define NSS 96
#define TT 8
#define HD 256
#define H4 1024
#define NW 1280
#define NN 97
#define NLAY 6
#define ROWS (BB*NN)     // 388
#define SEQS (BB*NSS)    // 384
#define TOK  (SEQS*TT)   // 3072

// ---------------- scratch -----------------------------------------------------
__device__ float g_xw[TOK*H4];         // token proj, GATE-INTERLEAVED [row][hh*4+g]
__device__ float g_Wt[HD*H4];          // Wh_s gate-interleaved [k][hh*4+g]
__device__ float g_Wxt[HD*H4];         // Wx_s gate-interleaved
__device__ float g_bst[H4];            // b_s gate-interleaved
__device__ float g_B1[HD*NW];          // [Wh_e | W_hk]
__device__ float g_B2[HD*NW];          // [Wx_e | W_sd]
__device__ float g_c0[SEQS*HD];
__device__ float g_hA[SEQS*HD];
__device__ float g_hB[SEQS*HD];
__device__ float g_pref[ROWS*HD];
__device__ float g_MeMs[HD*NW];
__device__ float g_pmS[ROWS*NW];       // cols 0-1023 = pm4, 1024+ = prS
__device__ float g_be[H4];
__device__ float g_bs[HD];
__device__ float g_S2[BB*NN*NN];
__device__ float g_u[ROWS*H4];
__device__ float g_hk[ROWS*HD];
__device__ float g_w[BB*NN*NN];
__device__ float g_cX[ROWS*HD], g_hX[ROWS*HD];
__device__ float g_cY[ROWS*HD], g_hY[ROWS*HD];
__device__ float g_pX[ROWS], g_pY[ROWS];

// exp-based gates (statement LSTM path)
__device__ __forceinline__ float sigf(float x) {
    return __fdividef(1.0f, 1.0f + __expf(-x));
}
__device__ __forceinline__ float tanhr(float x) {
    return 2.0f * __fdividef(1.0f, 1.0f + __expf(-2.0f * x)) - 1.0f;
}
// HW-tanh gates (agg hot loop)
__device__ __forceinline__ float tanhw(float x) {
    float y;
    asm("tanh.approx.f32 %0, %1;" : "=f"(y) : "f"(x));
    return y;
}
__device__ __forceinline__ float sigw(float x) {
    return fmaf(0.5f, tanhw(0.5f * x), 0.5f);
}

__device__ __forceinline__ float to_tf32(float x) {
    uint32_t o;
    asm("cvt.rna.tf32.f32 %0, %1;" : "=r"(o) : "f"(x));
    return __uint_as_float(o);
}

__device__ __forceinline__ void mma_tf32(float& c0, float& c1, float& c2, float& c3,
                                         float a0, float a1, float a2, float a3,
                                         float b0, float b1) {
    asm volatile(
        "mma.sync.aligned.m16n8k8.row.col.f32.tf32.tf32.f32 "
        "{%0,%1,%2,%3},{%4,%5,%6,%7},{%8,%9},{%0,%1,%2,%3};"
        : "+f"(c0), "+f"(c1), "+f"(c2), "+f"(c3)
        : "r"(__float_as_uint(a0)), "r"(__float_as_uint(a1)),
          "r"(__float_as_uint(a2)), "r"(__float_as_uint(a3)),
          "r"(__float_as_uint(b0)), "r"(__float_as_uint(b1)));
}

// ---------------- tf32 MMA GEMM, K=256, tile 64x64, double-buffered -----------
// EPI: 0 = plain (+opt bias), 1 = LSTM gates fused (xw interleaved), 2 = u + hk
#define SA_STRIDE 36
#define SB_STRIDE 72
#define BUF_STRIDE 68
#define TILE_FLOATS (64*SA_STRIDE + 32*SB_STRIDE)   // 4608
template<int EPI>
__global__ __launch_bounds__(256)
void mma_gemm(const float* __restrict__ A, const int* __restrict__ gidx,
              const float* __restrict__ B, const float* __restrict__ bias,
              float* __restrict__ C, int M, int N,
              const float* __restrict__ xw_t, float* __restrict__ c_st,
              float* __restrict__ hout,
              const float* __restrict__ be, const float* __restrict__ pmS,
              const float* __restrict__ b_hk, const float* __restrict__ W_d1,
              float* __restrict__ u, float* __restrict__ hkbuf) {
    __shared__ float smem[2 * TILE_FLOATS];
    const int tid = threadIdx.x;
    const int lane = tid & 31, warp = tid >> 5;
    const int wm = warp >> 1, wn = warp & 1;     // 4x2 warp grid
    const int g = lane >> 2, tg = lane & 3;
    const int bm = blockIdx.x * 64, bn = blockIdx.y * 64;

    // staging addresses (constant across k-iterations)
    const int ar_r  = tid >> 3;               // A rows handled by this thread (2x)
    const int ar_kc = (tid & 7) << 2;
    const int br_kk = tid >> 4;
    const int br_c  = (tid & 15) << 2;

    float4 va[2], vb[2];
    auto load_regs = [&](int k0) {
#pragma unroll
        for (int l = 0; l < 2; l++) {
            int r = ar_r + l * 32;
            int row = bm + r;
            float4 v = make_float4(0.f, 0.f, 0.f, 0.f);
            if (row < M) {
                int ar = gidx ? gidx[row] : row;
                v = *(const float4*)(A + (size_t)ar * HD + k0 + ar_kc);
            }
            va[l] = v;
        }
#pragma unroll
        for (int l = 0; l < 2; l++) {
            int kk = br_kk + l * 16;
            vb[l] = *(const float4*)(B + (size_t)(k0 + kk) * N + bn + br_c);
        }
    };
    auto store_smem = [&](int buf) {
        float* sA = smem + buf * TILE_FLOATS;
        float* sB = sA + 64 * SA_STRIDE;
#pragma unroll
        for (int l = 0; l < 2; l++) {
            float* d = sA + (ar_r + l * 32) * SA_STRIDE + ar_kc;
            d[0] = to_tf32(va[l].x); d[1] = to_tf32(va[l].y);
            d[2] = to_tf32(va[l].z); d[3] = to_tf32(va[l].w);
        }
#pragma unroll
        for (int l = 0; l < 2; l++) {
            float* d = sB + (br_kk + l * 16) * SB_STRIDE + br_c;
            d[0] = to_tf32(vb[l].x); d[1] = to_tf32(vb[l].y);
            d[2] = to_tf32(vb[l].z); d[3] = to_tf32(vb[l].w);
        }
    };

    float acc[4][4];
#pragma unroll
    for (int a = 0; a < 4; a++)
#pragma unroll
        for (int b = 0; b < 4; b++) acc[a][b] = 0.f;

    load_regs(0);
    store_smem(0);
    __syncthreads();

    constexpr int NT = HD / 32;   // 8 k-tiles
#pragma unroll
    for (int it = 0; it < NT; it++) {
        if (it + 1 < NT) load_regs((it + 1) * 32);
        const float* sA = smem + (it & 1) * TILE_FLOATS;
        const float* sB = sA + 64 * SA_STRIDE;
#pragma unroll
        for (int k8 = 0; k8 < 4; k8++) {
            int kb = k8 * 8;
            float a0 = sA[(wm * 16 + g) * SA_STRIDE + kb + tg];
            float a1 = sA[(wm * 16 + g + 8) * SA_STRIDE + kb + tg];
            float a2 = sA[(wm * 16 + g) * SA_STRIDE + kb + tg + 4];
            float a3 = sA[(wm * 16 + g + 8) * SA_STRIDE + kb + tg + 4];
#pragma unroll
            for (int nt = 0; nt < 4; nt++) {
                int nc = wn * 32 + nt * 8 + g;
                float b0 = sB[(kb + tg) * SB_STRIDE + nc];
                float b1 = sB[(kb + tg + 4) * SB_STRIDE + nc];
                mma_tf32(acc[nt][0], acc[nt][1], acc[nt][2], acc[nt][3],
                         a0, a1, a2, a3, b0, b1);
            }
        }
        if (it + 1 < NT) {
            store_smem((it + 1) & 1);
            __syncthreads();
        }
    }

    if (EPI == 1) {
        // stage accumulators to smem, regroup gates, apply LSTM (xw interleaved)
        __syncthreads();
        float* buf = smem;
#pragma unroll
        for (int nt = 0; nt < 4; nt++)
#pragma unroll
            for (int e = 0; e < 4; e++) {
                int lr = wm * 16 + g + ((e >> 1) ? 8 : 0);
                int lc = wn * 32 + nt * 8 + tg * 2 + (e & 1);
                buf[lr * BUF_STRIDE + lc] = acc[nt][e];
            }
        __syncthreads();
#pragma unroll
        for (int l = 0; l < 4; l++) {
            int pi = tid + l * 256;          // 1024 = 64 rows x 16 hidden
            int lr = pi & 63;
            int lh = pi >> 6;                // 0..15
            int row = bm + lr;
            int hh = (bn >> 2) + lh;         // global hidden unit
            float4 z4 = *(const float4*)(buf + lr * BUF_STRIDE + lh * 4);
            float4 x4 = *(const float4*)(xw_t + (size_t)row * (TT * H4) + hh * 4);
            float zi = z4.x + x4.x;
            float zf = z4.y + x4.y;
            float zg = z4.z + x4.z;
            float zo = z4.w + x4.w;
            size_t idx = (size_t)row * HD + hh;
            float cp = c_st[idx];
            float c2 = sigf(zf) * cp + sigf(zi) * tanhr(zg);
            c_st[idx] = c2;
            hout[idx] = sigf(zo) * tanhr(c2);
        }
        return;
    }

#pragma unroll
    for (int nt = 0; nt < 4; nt++)
#pragma unroll
        for (int e = 0; e < 4; e++) {
            int row = bm + wm * 16 + g + ((e >> 1) ? 8 : 0);
            int col = bn + wn * 32 + nt * 8 + tg * 2 + (e & 1);
            if (row >= M) continue;
            float v = acc[nt][e];
            if (EPI == 0) {
                C[(size_t)row * N + col] = v + (bias ? bias[col] : 0.f);
            } else {  // EPI == 2
                if (col < H4) {
                    u[(size_t)row * H4 + col] = v + be[col] - pmS[(size_t)row * NW + col];
                } else {
                    int cc = col - H4;
                    hkbuf[(size_t)row * HD + cc] =
                        fmaxf(v + b_hk[cc], 0.f) * W_d1[cc];
                }
            }
        }
}

// ---------------- merged prep: Wt, Wxt, bst, B1, B2, be, bs -------------------
__global__ void prep_kernel(const float* __restrict__ Wh_s, const float* __restrict__ Wx_s,
                            const float* __restrict__ b_s,
                            const float* __restrict__ Wh_e, const float* __restrict__ W_hk,
                            const float* __restrict__ Wx_e, const float* __restrict__ W_sd,
                            const float* __restrict__ b_se, const float* __restrict__ b_e,
                            const float* __restrict__ b_sd,
                            float* __restrict__ Wt, float* __restrict__ Wxt,
                            float* __restrict__ bst,
                            float* __restrict__ B1, float* __restrict__ B2,
                            float* __restrict__ be, float* __restrict__ bs) {
    int idx = blockIdx.x * 256 + threadIdx.x;
    if (idx < HD * H4) {
        int k = idx / H4, col = idx % H4;
        int g = col / HD, hh = col % HD;
        Wt[(size_t)k * H4 + hh * 4 + g] = Wh_s[idx];
        Wxt[(size_t)k * H4 + hh * 4 + g] = Wx_s[idx];
    }
    if (idx < H4) {
        int g = idx / HD, hh = idx % HD;
        bst[hh * 4 + g] = b_s[idx];
    }
    if (idx < HD * NW) {
        int k = idx / NW, c = idx % NW;
        B1[idx] = (c < H4) ? Wh_e[(size_t)k * H4 + c] : W_hk[(size_t)k * HD + (c - H4)];
        B2[idx] = (c < H4) ? Wx_e[(size_t)k * H4 + c] : W_sd[(size_t)k * HD + (c - H4)];
    }
    if (idx < H4) {
        float acc = b_e[idx];
        for (int k = 0; k < HD; k++) acc += b_se[k] * Wx_e[(size_t)k * H4 + idx];
        be[idx] = acc;
    } else if (idx < H4 + HD) {
        int c = idx - H4;
        float acc = b_sd[c];
        for (int k = 0; k < HD; k++) acc += b_se[k] * W_sd[(size_t)k * HD + c];
        bs[c] = acc;
    }
}

__global__ void lstm_gate0_kernel(const float* __restrict__ z, float* __restrict__ c,
                                  float* __restrict__ h) {
    int idx = blockIdx.x * blockDim.x + threadIdx.x;
    if (idx >= SEQS * HD) return;
    int s = idx / HD, hh = idx % HD;
    float4 z4 = *(const float4*)(z + (size_t)s * (TT * H4) + hh * 4);
    float zi = z4.x, zg = z4.z, zo = z4.w;
    float c2 = sigf(zi) * tanhr(zg);
    h[idx] = sigf(zo) * tanhr(c2);
    c[idx] = c2;
}

__global__ void cumsum_kernel(const float* __restrict__ stmt, float* __restrict__ pref) {
    int b = blockIdx.x, hh = threadIdx.x;
    float acc = 0.f;
    pref[(size_t)(b * NN) * HD + hh] = 0.f;
    for (int k = 1; k < NN; k++) {
        acc += stmt[(size_t)(b * NSS + k - 1) * HD + hh];
        pref[(size_t)(b * NN + k) * HD + hh] = acc;
    }
}

// S2 + exec-state init merged (grid = ROWS, 128 threads)
__global__ void s2_init_kernel(const float* __restrict__ pmS, const float* __restrict__ bs,
                               const float* __restrict__ W_d1, float* __restrict__ S2,
                               const float* __restrict__ ia, const float* __restrict__ ib,
                               float* __restrict__ cX, float* __restrict__ hX,
                               float* __restrict__ pX) {
    int bi = blockIdx.x;
    int b = bi / NN;
    int lane = threadIdx.x & 31, warp = threadIdx.x >> 5;
    // exec init for row bi
    for (int hh = threadIdx.x; hh < HD; hh += 128) {
        cX[(size_t)bi * HD + hh] = ia[hh];
        hX[(size_t)bi * HD + hh] = ib[hh];
    }
    if (threadIdx.x == 0) pX[bi] = (bi % NN == 0) ? 1.f : 0.f;
    // S2 row bi
    const float* pi = pmS + (size_t)bi * NW + H4;
    for (int j = warp; j < NN; j += 4) {
        const float* pj = pmS + (size_t)(b * NN + j) * NW + H4;
        float acc = 0.f;
#pragma unroll
        for (int l = 0; l < 8; l++) {
            int hh = lane + l * 32;
            float v = pj[hh] - pi[hh] + bs[hh];
            acc += fmaxf(v, 0.f) * W_d1[HD + hh];
        }
        for (int o = 16; o; o >>= 1) acc += __shfl_xor_sync(0xFFFFFFFFu, acc, o);
        if (lane == 0) S2[(size_t)bi * NN + j] = acc;
    }
}

// ---------------- per-layer: softmax ------------------------------------------
__global__ void softmax_kernel(const float* __restrict__ hkbuf,
                               const float* __restrict__ S2, const float* __restrict__ b_d1,
                               const float* __restrict__ p, const int* __restrict__ clen,
                               int layer, float* __restrict__ w) {
    int bi = blockIdx.x, b = bi / NN, i = bi % NN;
    int tid = threadIdx.x;   // 256
    __shared__ float red[256];
    red[tid] = hkbuf[(size_t)bi * HD + tid];
    __syncthreads();
    for (int s = 128; s > 0; s >>= 1) {
        if (tid < s) red[tid] += red[tid + s];
        __syncthreads();
    }
    float a = red[0];
    __syncthreads();

    int len = clen[b] / TT;
    int j = tid;
    bool m = false;
    if (j < NN) {
        if (layer == 0)             m = (j == 1);
        else if (layer == NLAY - 1) m = (j == len);
        else                        m = ((j > i) && (j <= len)) || (j == len);
    }
    float logit = m ? (a + S2[(size_t)bi * NN + j] + b_d1[0]) : -1e30f;
    red[tid] = logit; __syncthreads();
    for (int s = 128; s > 0; s >>= 1) {
        if (tid < s) red[tid] = fmaxf(red[tid], red[tid + s]);
        __syncthreads();
    }
    float mx = red[0]; __syncthreads();
    float e = m ? __expf(logit - mx) : 0.f;
    red[tid] = e; __syncthreads();
    for (int s = 128; s > 0; s >>= 1) {
        if (tid < s) red[tid] += red[tid + s];
        __syncthreads();
    }
    float sum = red[0];
    if (j < NN) w[(size_t)bi * NN + j] = p[bi] * __fdividef(e, sum);
}

// ---------------- per-layer: gated aggregation (HW tanh gates) ----------------
__global__ void agg_kernel(const float* __restrict__ w, const float* __restrict__ pmS,
                           const float* __restrict__ u,
                           const float* __restrict__ cIn, const float* __restrict__ hIn,
                           float* __restrict__ cOut, float* __restrict__ hOut,
                           float* __restrict__ pOut) {
    int bj = blockIdx.x, b = bj / NN, j = bj % NN;
    int hh = threadIdx.x;  // 256
    __shared__ float sw[NN];
    if (hh < NN) sw[hh] = w[((size_t)(b * NN + hh)) * NN + j];
    __syncthreads();
    const float* pj = pmS + (size_t)bj * NW;
    float zj0 = pj[hh], zj1 = pj[HD + hh], zj2 = pj[2 * HD + hh], zj3 = pj[3 * HD + hh];
    float accC = 0.f, accH = 0.f, wsum = 0.f;
    for (int i = 0; i < NN; i++) {
        float wi = sw[i];
        wsum += wi;
        if (wi == 0.f) continue;
        int ri = b * NN + i;
        float cp, hp;
        if (j > i) {
            const float* ui = u + (size_t)ri * H4;
            float zi = zj0 + ui[hh];
            float zf = zj1 + ui[HD + hh];
            float zg = zj2 + ui[2 * HD + hh];
            float zo = zj3 + ui[3 * HD + hh];
            float cold = cIn[(size_t)ri * HD + hh];
            cp = sigw(zf) * cold + sigw(zi) * tanhw(zg);
            hp = sigw(zo) * tanhw(cp);
        } else {
            cp = cIn[(size_t)ri * HD + hh];
            hp = hIn[(size_t)ri * HD + hh];
        }
        accC += wi * cp;
        accH += wi * hp;
    }
    float inv = __fdividef(1.f, wsum + 1e-7f);
    cOut[(size_t)bj * HD + hh] = accC * inv;
    hOut[(size_t)bj * HD + hh] = accH * inv;
    if (hh == 0) pOut[bj] = wsum;
}

// ------------------------------------------------------------------------------
static float* sym(const void* s) {
    void* p = nullptr;
    cudaGetSymbolAddress(&p, s);
    return (float*)p;
}

extern "C" void kernel_launch(void* const* d_in, const int* in_sizes, int n_in,
                              void* d_out, int out_size) {
    const int*   ids    = (const int*)d_in[0];
    const int*   clen   = (const int*)d_in[1];
    const float* embed  = (const float*)d_in[2];
    const float* Wx_s   = (const float*)d_in[3];
    const float* Wh_s   = (const float*)d_in[4];
    const float* b_s    = (const float*)d_in[5];
    const float* W_se   = (const float*)d_in[6];
    const float* b_se   = (const float*)d_in[7];
    const float* Wx_e   = (const float*)d_in[8];
    const float* Wh_e   = (const float*)d_in[9];
    const float* b_e    = (const float*)d_in[10];
    const float* W_hk   = (const float*)d_in[11];
    const float* b_hk   = (const float*)d_in[12];
    const float* W_sd   = (const float*)d_in[13];
    const float* b_sd   = (const float*)d_in[14];
    const float* W_d1   = (const float*)d_in[15];
    const float* b_d1   = (const float*)d_in[16];
    const float* init_a = (const float*)d_in[17];
    const float* init_b = (const float*)d_in[18];

    float* xw   = sym(g_xw);
    float* Wt   = sym(g_Wt);
    float* Wxt  = sym(g_Wxt);
    float* bst  = sym(g_bst);
    float* B1   = sym(g_B1);
    float* B2   = sym(g_B2);
    float* c0   = sym(g_c0);
    float* hA   = sym(g_hA);
    float* hB   = sym(g_hB);
    float* pref = sym(g_pref);
    float* MeMs = sym(g_MeMs);
    float* pmS  = sym(g_pmS);
    float* be   = sym(g_be);
    float* bs   = sym(g_bs);
    float* S2   = sym(g_S2);
    float* uBuf = sym(g_u);
    float* hk   = sym(g_hk);
    float* wM   = sym(g_w);
    float* cX   = sym(g_cX);
    float* hX   = sym(g_hX);
    float* cY   = sym(g_cY);
    float* hY   = sym(g_hY);
    float* pX   = sym(g_pX);
    float* pY   = sym(g_pY);

    // 0) merged prep
    prep_kernel<<<(HD * NW + 255) / 256, 256>>>(
        Wh_s, Wx_s, b_s, Wh_e, W_hk, Wx_e, W_sd, b_se, b_e, b_sd,
        Wt, Wxt, bst, B1, B2, be, bs);

    // 1) token projection (gate-interleaved output)
    mma_gemm<0><<<dim3(TOK / 64, H4 / 64), 256>>>(
        embed, ids, Wxt, bst, xw, TOK, H4,
        nullptr, nullptr, nullptr, nullptr, nullptr, nullptr, nullptr, nullptr, nullptr);

    // 2) statement LSTM
    lstm_gate0_kernel<<<(SEQS * HD + 255) / 256, 256>>>(xw, c0, hA);
    float *hs = hA, *hd = hB;
    for (int t = 1; t < TT; t++) {
        mma_gemm<1><<<dim3(SEQS / 64, H4 / 64), 256>>>(
            hs, nullptr, Wt, nullptr, nullptr, SEQS, H4,
            xw + (size_t)t * H4, c0, hd,
            nullptr, nullptr, nullptr, nullptr, nullptr, nullptr);
        float* tmp = hs; hs = hd; hd = tmp;
    }

    // 3) prefix sums
    cumsum_kernel<<<BB, HD>>>(hs, pref);

    // 4) composed tables
    mma_gemm<0><<<dim3(HD / 64, NW / 64), 256>>>(
        W_se, nullptr, B2, nullptr, MeMs, HD, NW,
        nullptr, nullptr, nullptr, nullptr, nullptr, nullptr, nullptr, nullptr, nullptr);
    mma_gemm<0><<<dim3((ROWS + 63) / 64, NW / 64), 256>>>(
        pref, nullptr, MeMs, nullptr, pmS, ROWS, NW,
        nullptr, nullptr, nullptr, nullptr, nullptr, nullptr, nullptr, nullptr, nullptr);

    // 5) S2 + exec init merged
    s2_init_kernel<<<ROWS, 128>>>(pmS, bs, W_d1, S2, init_a, init_b, cX, hX, pX);

    // 6) execution layers
    float *cS = cX, *hS = hX, *pS = pX, *cD = cY, *hD2 = hY, *pD = pY;
    for (int layer = 0; layer < NLAY; layer++) {
        mma_gemm<2><<<dim3((ROWS + 63) / 64, NW / 64), 256>>>(
            hS, nullptr, B1, nullptr, nullptr, ROWS, NW,
            nullptr, nullptr, nullptr,
            be, pmS, b_hk, W_d1, uBuf, hk);
        softmax_kernel<<<ROWS, 256>>>(hk, S2, b_d1, pS, clen, layer, wM);
        float* hOutPtr = (layer == NLAY - 1) ? (float*)d_out : hD2;
        agg_kernel<<<ROWS, 256>>>(wM, pmS, uBuf, cS, hS, cD, hOutPtr, pD);
        float* t;
        t = cS; cS = cD; cD = t;
        t = hS; hS = hD2; hD2 = t;
        t = pS; pS = pD; pD = t;
    }
}